// round 15
// baseline (speedup 1.0000x reference)
#include <cuda_runtime.h>
#include <cuda_bf16.h>
#include <cuda_fp16.h>
#include <cstdint>

#define B_SZ   1024
#define T_SZ   256
#define F_SZ   256
#define H_SZ   64
#define G4H    256

// ---------------------------------------------------------------------------
// Scratch (device globals)
// ---------------------------------------------------------------------------
__device__ float    g_xw0[(size_t)T_SZ * B_SZ * G4H];   // [T,B,4H]
__device__ float    g_hout[(size_t)B_SZ * H_SZ];
__device__ float    g_mean[H_SZ];
__device__ float    g_rstd[H_SZ];
__device__ uint32_t g_wprep[4 * 2 * 64 * 128];          // Wih0 hi/lo f16x2, GEMM-smem layout

// ---------------------------------------------------------------------------
// helpers
// ---------------------------------------------------------------------------
__device__ __forceinline__ float sigf(float x) {
    return __fdividef(1.f, 1.f + __expf(-x));
}
__device__ __forceinline__ float tanhfast(float x) {
    return 2.f * __fdividef(1.f, 1.f + __expf(-2.f * x)) - 1.f;
}

// pack two floats to half2 (x -> low = even k)
__device__ __forceinline__ uint32_t f2h2(float x, float y) {
    __half2 h = __floats2half2_rn(x, y);
    return *(uint32_t*)&h;
}
// fp16 hi/lo split: v = hi + lo with ~22 effective mantissa bits
__device__ __forceinline__ void cvt_hilo_h(float x, float y, uint32_t& hi, uint32_t& lo) {
    __half2 h = __floats2half2_rn(x, y);
    float rx = x - __half2float(__low2half(h));
    float ry = y - __half2float(__high2half(h));
    __half2 l = __floats2half2_rn(rx, ry);
    hi = *(uint32_t*)&h;
    lo = *(uint32_t*)&l;
}

// m16n8k16 row.col fp16 MMA, f32 accum
__device__ __forceinline__ void mma16816(float* c, const uint32_t* a, uint32_t b0, uint32_t b1) {
    asm volatile(
        "mma.sync.aligned.m16n8k16.row.col.f32.f16.f16.f32 "
        "{%0,%1,%2,%3}, {%4,%5,%6,%7}, {%8,%9}, {%0,%1,%2,%3};\n"
        : "+f"(c[0]), "+f"(c[1]), "+f"(c[2]), "+f"(c[3])
        : "r"(a[0]), "r"(a[1]), "r"(a[2]), "r"(a[3]), "r"(b0), "r"(b1));
}

// ---------------------------------------------------------------------------
// Kernel 0: pre-convert Wih0 -> hi/lo f16x2 planes (GEMM Bs layout)
// ---------------------------------------------------------------------------
__global__ __launch_bounds__(256) void prep_w(
    const float* __restrict__ Wih0, uint32_t* __restrict__ wprep)
{
    int u = blockIdx.x * 256 + threadIdx.x;
    int n = u >> 3, kg = u & 7;
    int nc = n >> 6, r = n & 63;
#pragma unroll
    for (int j = 0; j < 16; j++) {
        int p = kg * 16 + j;
        float2 v = *(const float2*)(Wih0 + (size_t)n * F_SZ + 2 * p);
        uint32_t hi, lo;
        cvt_hilo_h(v.x, v.y, hi, lo);
        wprep[((nc * 2 + 0) * 64 + r) * 128 + p] = hi;
        wprep[((nc * 2 + 1) * 64 + r) * 128 + p] = lo;
    }
}

// ---------------------------------------------------------------------------
// Kernel 1: input projection GEMM, fp16 2-MMA scheme (validated R13; unchanged)
// ---------------------------------------------------------------------------
#define AS_STR 132
#define GEMM_SMEM_U32 (128*AS_STR + 2*64*AS_STR + 256)

__global__ __launch_bounds__(256) void input_gemm(
    const float* __restrict__ x,
    const uint32_t* __restrict__ wprep,
    const float* __restrict__ bih0,
    const float* __restrict__ bhh0,
    float* __restrict__ xw0)
{
    extern __shared__ uint32_t smu[];
    uint32_t* As    = smu;                        // [128][132] x as half2
    uint32_t* Bs_hi = As + 128 * AS_STR;          // [64][132]
    uint32_t* Bs_lo = Bs_hi + 64 * AS_STR;
    float*    sbias = (float*)(Bs_lo + 64 * AS_STR);

    const int tid  = threadIdx.x;
    const int lane = tid & 31;
    const int wid  = tid >> 5;
    const int wm   = wid & 3;
    const int wn   = wid >> 2;
    const int g    = lane >> 2;
    const int t4   = lane & 3;
    const int m0   = blockIdx.x * 128;
    const int tt   = m0 >> 10;

    sbias[tid] = bih0[tid] + bhh0[tid];

    {
        int row = tid >> 1, half = tid & 1;
        int b   = (m0 + row) & 1023;
        const float4* src = (const float4*)(x + ((size_t)b * T_SZ + tt) * F_SZ + half * 128);
        uint32_t* d = As + row * AS_STR + half * 64;
#pragma unroll 8
        for (int q = 0; q < 32; q++) {
            float4 v = src[q];
            d[2 * q]     = f2h2(v.x, v.y);
            d[2 * q + 1] = f2h2(v.z, v.w);
        }
    }

    for (int nc = 0; nc < 4; nc++) {
        const int n0 = nc * 64;
        {
            int row = tid >> 2, q4 = tid & 3;
            const float4* shi = (const float4*)(wprep + ((nc * 2 + 0) * 64 + row) * 128 + q4 * 32);
            const float4* slo = (const float4*)(wprep + ((nc * 2 + 1) * 64 + row) * 128 + q4 * 32);
            float4* dhi = (float4*)(Bs_hi + row * AS_STR + q4 * 32);
            float4* dlo = (float4*)(Bs_lo + row * AS_STR + q4 * 32);
#pragma unroll
            for (int q = 0; q < 8; q++) { dhi[q] = shi[q]; dlo[q] = slo[q]; }
        }
        __syncthreads();

        float acc[2][4][4];
#pragma unroll
        for (int mi = 0; mi < 2; mi++)
#pragma unroll
            for (int ni = 0; ni < 4; ni++)
#pragma unroll
                for (int q = 0; q < 4; q++) acc[mi][ni][q] = 0.f;

#pragma unroll 4
        for (int ks = 0; ks < 16; ks++) {
            uint32_t a[2][4];
#pragma unroll
            for (int mi = 0; mi < 2; mi++) {
                const uint32_t* p = As + (wm * 32 + mi * 16 + g) * AS_STR + ks * 8 + t4;
                a[mi][0] = p[0];            a[mi][2] = p[4];
                a[mi][1] = p[8 * AS_STR];   a[mi][3] = p[8 * AS_STR + 4];
            }
#pragma unroll
            for (int ni = 0; ni < 4; ni++) {
                int n = wn * 32 + ni * 8 + g;
                uint32_t bh0 = Bs_hi[n * AS_STR + ks * 8 + t4];
                uint32_t bh1 = Bs_hi[n * AS_STR + ks * 8 + t4 + 4];
                uint32_t bl0 = Bs_lo[n * AS_STR + ks * 8 + t4];
                uint32_t bl1 = Bs_lo[n * AS_STR + ks * 8 + t4 + 4];
#pragma unroll
                for (int mi = 0; mi < 2; mi++) {
                    mma16816(acc[mi][ni], a[mi], bh0, bh1);
                    mma16816(acc[mi][ni], a[mi], bl0, bl1);
                }
            }
        }

#pragma unroll
        for (int mi = 0; mi < 2; mi++) {
#pragma unroll
            for (int ni = 0; ni < 4; ni++) {
                int r  = wm * 32 + mi * 16 + g;
                int cl = n0 + wn * 32 + ni * 8 + 2 * t4;
                size_t m = (size_t)(m0 + r);
                xw0[m * G4H + cl]           = acc[mi][ni][0] + sbias[cl];
                xw0[m * G4H + cl + 1]       = acc[mi][ni][1] + sbias[cl + 1];
                xw0[(m + 8) * G4H + cl]     = acc[mi][ni][2] + sbias[cl];
                xw0[(m + 8) * G4H + cl + 1] = acc[mi][ni][3] + sbias[cl + 1];
            }
        }
        __syncthreads();
    }
}

// ---------------------------------------------------------------------------
// Kernel 2: fused 2-layer LSTM recurrence, v5: k-sliced N-tiling.
// Warp w owns n-columns {ntl*64 + 8w + g}: thread (g,t4) receives ALL FOUR
// gates for (row g, k=8w+2t4) directly in its MMA fragment -> in-register
// gates, zero z-smem, 2 barriers/step, h double-buffered.
// ---------------------------------------------------------------------------
#define LROWS 8
// smem u32: W2hi 8192 | W2lo 8192 | h0[2][288] | h1[2][288] | bias 256
#define LSTM5_SMEM_U32 (16384 + 4*288 + 256)

__global__ __launch_bounds__(256, 1) void lstm_mma(
    const float* __restrict__ xw0,
    const float* __restrict__ Whh0,
    const float* __restrict__ Wih1,
    const float* __restrict__ Whh1,
    const float* __restrict__ bih1,
    const float* __restrict__ bhh1,
    float* __restrict__ hout)
{
    extern __shared__ uint32_t su[];
    uint32_t* W2hi  = su;
    uint32_t* W2lo  = su + 8192;
    uint32_t* h0buf = su + 16384;            // [2][288] half2
    uint32_t* h1buf = su + 16384 + 576;      // [2][288]
    float*    sbias = (float*)(su + 16384 + 1152);   // [256]

    const int tid  = threadIdx.x;
    const int lane = tid & 31;
    const int w    = tid >> 5;       // warp 0..7 -> k-slice [8w, 8w+8)
    const int g    = lane >> 2;      // row 0..7
    const int t4   = lane & 3;
    const int b0   = blockIdx.x * LROWS;
    const int kp   = 4 * w + t4;     // thread's h kpair (0..31)
    const int kk   = 8 * w + 2 * t4; // thread's k (even)

    // ---- one-time: W2 hi/lo into swizzled smem B-layout ----
    for (int p = tid; p < 8192; p += 256) {
        int n = p >> 5, kpp = p & 31;
        float2 v = *(const float2*)(Whh1 + (size_t)n * 64 + 2 * kpp);
        uint32_t hi, lo;
        cvt_hilo_h(v.x, v.y, hi, lo);
        int col = kpp ^ ((n & 7) << 2);
        W2hi[n * 32 + col] = hi;
        W2lo[n * 32 + col] = lo;
    }
    sbias[tid] = bih1[tid] + bhh1[tid];
    for (int i = tid; i < 1152; i += 256) su[16384 + i] = 0;   // zero h state

    // ---- one-time: W0/W1 hi/lo B-fragments into registers ----
    // n = ntl*64 + 8w + g ; [kt][ntl][pos(b0,b1)][hi,lo]
    uint32_t w0f[4][4][2][2], w1f[4][4][2][2];
#pragma unroll
    for (int kt = 0; kt < 4; kt++)
#pragma unroll
        for (int ntl = 0; ntl < 4; ntl++) {
            int n  = ntl * 64 + 8 * w + g;
            int p0 = 8 * kt + t4;
            float2 v0 = *(const float2*)(Whh0 + (size_t)n * 64 + 2 * p0);
            float2 v1 = *(const float2*)(Whh0 + (size_t)n * 64 + 2 * (p0 + 4));
            cvt_hilo_h(v0.x, v0.y, w0f[kt][ntl][0][0], w0f[kt][ntl][0][1]);
            cvt_hilo_h(v1.x, v1.y, w0f[kt][ntl][1][0], w0f[kt][ntl][1][1]);
            float2 u0 = *(const float2*)(Wih1 + (size_t)n * 64 + 2 * p0);
            float2 u1 = *(const float2*)(Wih1 + (size_t)n * 64 + 2 * (p0 + 4));
            cvt_hilo_h(u0.x, u0.y, w1f[kt][ntl][0][0], w1f[kt][ntl][0][1]);
            cvt_hilo_h(u1.x, u1.y, w1f[kt][ntl][1][0], w1f[kt][ntl][1][1]);
        }
    __syncthreads();

    // gate-phase constants at this thread's (gate base + kk)
    float2 bz[4];
#pragma unroll
    for (int gi = 0; gi < 4; gi++)
        bz[gi] = *(const float2*)&sbias[gi * 64 + kk];

    float c0x = 0.f, c0y = 0.f, c1x = 0.f, c1y = 0.f;

    const float* xrow = xw0 + (size_t)(b0 + g) * G4H + kk;
    float2 xq[4];
#pragma unroll
    for (int gi = 0; gi < 4; gi++) xq[gi] = *(const float2*)(xrow + gi * 64);

    for (int t = 0; t < T_SZ; t++) {
        const uint32_t* h0r = h0buf + (t & 1) * 288;
        uint32_t*       h0w = h0buf + ((t + 1) & 1) * 288;
        const uint32_t* h1r = h1buf + (t & 1) * 288;
        uint32_t*       h1w = h1buf + ((t + 1) & 1) * 288;

        // ======= phase A: z0 = Whh0 @ h0_old (in-fragment) + gates0 ======
        float acc0[4][4];
#pragma unroll
        for (int ntl = 0; ntl < 4; ntl++)
#pragma unroll
            for (int q = 0; q < 4; q++) acc0[ntl][q] = 0.f;

#pragma unroll
        for (int kt = 0; kt < 4; kt++) {
            uint32_t a[4];
            {
                const uint32_t* p = h0r + g * 36 + kt * 8 + t4;
                a[0] = p[0]; a[1] = 0u; a[2] = p[4]; a[3] = 0u;
            }
#pragma unroll
            for (int ntl = 0; ntl < 4; ntl++) {
                mma16816(acc0[ntl], a, w0f[kt][ntl][0][0], w0f[kt][ntl][1][0]);
                mma16816(acc0[ntl], a, w0f[kt][ntl][0][1], w0f[kt][ntl][1][1]);
            }
        }
        // gates0: acc0[ntl][0/1] = z_gate_ntl(row g, k = kk/kk+1) -- in-register
        {
            float hx, hy;
            {
                float vi = acc0[0][0] + xq[0].x, vf = acc0[1][0] + xq[1].x;
                float vg = acc0[2][0] + xq[2].x, vo = acc0[3][0] + xq[3].x;
                c0x = sigf(vf) * c0x + sigf(vi) * tanhfast(vg);
                hx = sigf(vo) * tanhfast(c0x);
            }
            {
                float vi = acc0[0][1] + xq[0].y, vf = acc0[1][1] + xq[1].y;
                float vg = acc0[2][1] + xq[2].y, vo = acc0[3][1] + xq[3].y;
                c0y = sigf(vf) * c0y + sigf(vi) * tanhfast(vg);
                hy = sigf(vo) * tanhfast(c0y);
            }
            h0w[g * 36 + kp] = f2h2(hx, hy);
        }
        __syncthreads();   // B1: h0_new visible

        // ======= phase B: z1 = Whh1 @ h1_old + Wih1 @ h0_new + gates1 ====
        float acc1[4][4];
#pragma unroll
        for (int ntl = 0; ntl < 4; ntl++)
#pragma unroll
            for (int q = 0; q < 4; q++) acc1[ntl][q] = 0.f;

#pragma unroll
        for (int kt = 0; kt < 4; kt++) {
            uint32_t a[4];
            {
                const uint32_t* p = h1r + g * 36 + kt * 8 + t4;
                a[0] = p[0]; a[1] = 0u; a[2] = p[4]; a[3] = 0u;
            }
            const int cA = (kt * 8 + t4) ^ (g << 2);
            const int cB = (kt * 8 + t4 + 4) ^ (g << 2);
#pragma unroll
            for (int ntl = 0; ntl < 4; ntl++) {
                int n = ntl * 64 + 8 * w + g;
                uint32_t bh0 = W2hi[n * 32 + cA], bh1 = W2hi[n * 32 + cB];
                uint32_t bl0 = W2lo[n * 32 + cA], bl1 = W2lo[n * 32 + cB];
                mma16816(acc1[ntl], a, bh0, bh1);
                mma16816(acc1[ntl], a, bl0, bl1);
            }
        }
#pragma unroll
        for (int kt = 0; kt < 4; kt++) {
            uint32_t a[4];
            {
                const uint32_t* p = h0w + g * 36 + kt * 8 + t4;
                a[0] = p[0]; a[1] = 0u; a[2] = p[4]; a[3] = 0u;
            }
#pragma unroll
            for (int ntl = 0; ntl < 4; ntl++) {
                mma16816(acc1[ntl], a, w1f[kt][ntl][0][0], w1f[kt][ntl][1][0]);
                mma16816(acc1[ntl], a, w1f[kt][ntl][0][1], w1f[kt][ntl][1][1]);
            }
        }
        // gates1 (in-register)
        {
            float hx, hy;
            {
                float vi = acc1[0][0] + bz[0].x, vf = acc1[1][0] + bz[1].x;
                float vg = acc1[2][0] + bz[2].x, vo = acc1[3][0] + bz[3].x;
                c1x = sigf(vf) * c1x + sigf(vi) * tanhfast(vg);
                hx = sigf(vo) * tanhfast(c1x);
            }
            {
                float vi = acc1[0][1] + bz[0].y, vf = acc1[1][1] + bz[1].y;
                float vg = acc1[2][1] + bz[2].y, vo = acc1[3][1] + bz[3].y;
                c1y = sigf(vf) * c1y + sigf(vi) * tanhfast(vg);
                hy = sigf(vo) * tanhfast(c1y);
            }
            h1w[g * 36 + kp] = f2h2(hx, hy);
            if (t == T_SZ - 1)
                *(float2*)&hout[(size_t)(b0 + g) * H_SZ + kk] = make_float2(hx, hy);
        }
        if (t < T_SZ - 1) {
            size_t off = (size_t)(t + 1) * ((size_t)B_SZ * G4H);
#pragma unroll
            for (int gi = 0; gi < 4; gi++) xq[gi] = *(const float2*)(xrow + off + gi * 64);
        }
        __syncthreads();   // B2: h1_new visible; buffers safe to rotate
    }
}

// ---------------------------------------------------------------------------
// Kernel 3: batchnorm statistics
// ---------------------------------------------------------------------------
__global__ __launch_bounds__(256) void bn_stats(
    const float* __restrict__ h, float* __restrict__ mean, float* __restrict__ rstd)
{
    const int k = blockIdx.x;
    __shared__ float s1[256], s2[256];
    float a = 0.f, b = 0.f;
    for (int i = threadIdx.x; i < B_SZ; i += 256) {
        float v = h[(size_t)i * H_SZ + k];
        a += v; b += v * v;
    }
    s1[threadIdx.x] = a; s2[threadIdx.x] = b;
    __syncthreads();
    for (int s = 128; s > 0; s >>= 1) {
        if (threadIdx.x < s) { s1[threadIdx.x] += s1[threadIdx.x + s]; s2[threadIdx.x] += s2[threadIdx.x + s]; }
        __syncthreads();
    }
    if (threadIdx.x == 0) {
        float m = s1[0] / (float)B_SZ;
        float var = s2[0] / (float)B_SZ - m * m;
        mean[k] = m;
        rstd[k] = rsqrtf(var + 1e-5f);
    }
}

// ---------------------------------------------------------------------------
// Kernel 4: BN apply + MLP trunk + 3 heads
// ---------------------------------------------------------------------------
__global__ __launch_bounds__(256) void mlp_head(
    const float* __restrict__ hbuf,
    const float* __restrict__ mean, const float* __restrict__ rstd,
    const float* __restrict__ gamma, const float* __restrict__ beta,
    const float* __restrict__ W1, const float* __restrict__ b1,
    const float* __restrict__ W2, const float* __restrict__ b2,
    const float* __restrict__ Wmc, const float* __restrict__ bmc,
    const float* __restrict__ Wco, const float* __restrict__ bco,
    const float* __restrict__ Wip, const float* __restrict__ bip,
    float* __restrict__ out)
{
    __shared__ float sH[32][64];
    __shared__ float sY1[32][64];
    __shared__ float sY2[32][32];
    __shared__ float sW1[64 * 64];
    __shared__ float sW2[32 * 64];
    __shared__ float sWh[7 * 32];
    __shared__ float sB1[64], sB2[32], sBh[7];

    const int tid = threadIdx.x;
    const int r0  = blockIdx.x * 32;

    for (int i = tid; i < 64 * 64; i += 256) sW1[i] = W1[i];
    for (int i = tid; i < 32 * 64; i += 256) sW2[i] = W2[i];
    for (int i = tid; i < 7 * 32; i += 256)
        sWh[i] = (i < 96) ? Wmc[i] : (i < 160 ? Wco[i - 96] : Wip[i - 160]);
    if (tid < 64) sB1[tid] = b1[tid];
    if (tid < 32) sB2[tid] = b2[tid];
    if (tid < 7)  sBh[tid] = (tid < 3) ? bmc[tid] : (tid < 5 ? bco[tid - 3] : bip[tid - 5]);

    for (int i = tid; i < 32 * 64; i += 256) {
        int r = i >> 6, k = i & 63;
        float v = hbuf[(size_t)(r0 + r) * 64 + k];
        sH[r][k] = (v - mean[k]) * rstd[k] * gamma[k] + beta[k];
    }
    __syncthreads();

    for (int i = tid; i < 32 * 64; i += 256) {
        int r = i >> 6, o = i & 63;
        float a = sB1[o];
#pragma unroll
        for (int k = 0; k < 64; k++) a += sW1[o * 64 + k] * sH[r][k];
        sY1[r][o] = fmaxf(a, 0.f);
    }
    __syncthreads();

    for (int i = tid; i < 32 * 32; i += 256) {
        int r = i >> 5, o = i & 31;
        float a = sB2[o];
#pragma unroll
        for (int k = 0; k < 64; k++) a += sW2[o * 64 + k] * sY1[r][k];
        sY2[r][o] = fmaxf(a, 0.f);
    }
    __syncthreads();

    for (int i = tid; i < 32 * 7; i += 256) {
        int r = i / 7, o = i % 7;
        float a = sBh[o];
#pragma unroll
        for (int k = 0; k < 32; k++) a += sWh[o * 32 + k] * sY2[r][k];
        int row = r0 + r;
        if (o < 3)       out[(size_t)row * 3 + o] = a;
        else if (o < 5)  out[3072 + (size_t)row * 2 + (o - 3)] = a;
        else             out[5120 + (size_t)row * 2 + (o - 5)] = a;
    }
}

// ---------------------------------------------------------------------------
// Launch
// ---------------------------------------------------------------------------
extern "C" void kernel_launch(void* const* d_in, const int* in_sizes, int n_in,
                              void* d_out, int out_size)
{
    const float* x      = (const float*)d_in[0];
    const float* Wih0   = (const float*)d_in[1];
    const float* Whh0   = (const float*)d_in[2];
    const float* bih0   = (const float*)d_in[3];
    const float* bhh0   = (const float*)d_in[4];
    const float* Wih1   = (const float*)d_in[5];
    const float* Whh1   = (const float*)d_in[6];
    const float* bih1   = (const float*)d_in[7];
    const float* bhh1   = (const float*)d_in[8];
    const float* gamma  = (const float*)d_in[9];
    const float* beta   = (const float*)d_in[10];
    const float* W_fc1  = (const float*)d_in[11];
    const float* b_fc1  = (const float*)d_in[12];
    const float* W_fc2  = (const float*)d_in[13];
    const float* b_fc2  = (const float*)d_in[14];
    const float* W_mc   = (const float*)d_in[15];
    const float* b_mc   = (const float*)d_in[16];
    const float* W_co   = (const float*)d_in[17];
    const float* b_co   = (const float*)d_in[18];
    const float* W_ip   = (const float*)d_in[19];
    const float* b_ip   = (const float*)d_in[20];
    float* out = (float*)d_out;

    float* xw0;       cudaGetSymbolAddress((void**)&xw0,   g_xw0);
    float* hout;      cudaGetSymbolAddress((void**)&hout,  g_hout);
    float* mean;      cudaGetSymbolAddress((void**)&mean,  g_mean);
    float* rstd;      cudaGetSymbolAddress((void**)&rstd,  g_rstd);
    uint32_t* wprep;  cudaGetSymbolAddress((void**)&wprep, g_wprep);

    // 0. pre-convert Wih0 -> hi/lo f16x2 (GEMM B layout)
    prep_w<<<8, 256>>>(Wih0, wprep);

    // 1. input projection GEMM (fp16 2-MMA)
    {
        size_t smem = (size_t)GEMM_SMEM_U32 * sizeof(uint32_t);
        cudaFuncSetAttribute(input_gemm, cudaFuncAttributeMaxDynamicSharedMemorySize, (int)smem);
        input_gemm<<<(T_SZ * B_SZ) / 128, 256, smem>>>(x, wprep, bih0, bhh0, xw0);
    }

    // 2. fused 2-layer recurrence (fp16 2-MMA, k-sliced tiling, 2 barriers/step)
    {
        size_t smem = (size_t)LSTM5_SMEM_U32 * sizeof(uint32_t);
        cudaFuncSetAttribute(lstm_mma, cudaFuncAttributeMaxDynamicSharedMemorySize, (int)smem);
        lstm_mma<<<B_SZ / LROWS, 256, smem>>>(xw0, Whh0, Wih1, Whh1, bih1, bhh1, hout);
    }

    // 3. batchnorm statistics
    bn_stats<<<H_SZ, 256>>>(hout, mean, rstd);

    // 4. BN apply + MLP + heads
    mlp_head<<<B_SZ / 32, 256>>>(hout, mean, rstd, gamma, beta,
                                 W_fc1, b_fc1, W_fc2, b_fc2,
                                 W_mc, b_mc, W_co, b_co, W_ip, b_ip, out);
}

// round 17
// speedup vs baseline: 1.2197x; 1.2197x over previous
#include <cuda_runtime.h>
#include <cuda_bf16.h>
#include <cuda_fp16.h>
#include <cstdint>

#define B_SZ   1024
#define T_SZ   256
#define F_SZ   256
#define H_SZ   64
#define G4H    256

// ---------------------------------------------------------------------------
// Scratch (device globals)
// ---------------------------------------------------------------------------
__device__ float    g_xw0[(size_t)T_SZ * B_SZ * G4H];   // [T,B,4H]
__device__ float    g_hout[(size_t)B_SZ * H_SZ];
__device__ float    g_mean[H_SZ];
__device__ float    g_rstd[H_SZ];
__device__ uint32_t g_wprep[4 * 2 * 64 * 128];          // Wih0 hi/lo f16x2, GEMM-smem layout

// ---------------------------------------------------------------------------
// helpers
// ---------------------------------------------------------------------------
__device__ __forceinline__ float sigf(float x) {
    return __fdividef(1.f, 1.f + __expf(-x));
}
__device__ __forceinline__ float tanhfast(float x) {
    return 2.f * __fdividef(1.f, 1.f + __expf(-2.f * x)) - 1.f;
}

// pack two floats to half2 (x -> low = even k)
__device__ __forceinline__ uint32_t f2h2(float x, float y) {
    __half2 h = __floats2half2_rn(x, y);
    return *(uint32_t*)&h;
}
// fp16 hi/lo split: v = hi + lo with ~22 effective mantissa bits
__device__ __forceinline__ void cvt_hilo_h(float x, float y, uint32_t& hi, uint32_t& lo) {
    __half2 h = __floats2half2_rn(x, y);
    float rx = x - __half2float(__low2half(h));
    float ry = y - __half2float(__high2half(h));
    __half2 l = __floats2half2_rn(rx, ry);
    hi = *(uint32_t*)&h;
    lo = *(uint32_t*)&l;
}

// m16n8k16 row.col fp16 MMA, f32 accum
__device__ __forceinline__ void mma16816(float* c, const uint32_t* a, uint32_t b0, uint32_t b1) {
    asm volatile(
        "mma.sync.aligned.m16n8k16.row.col.f32.f16.f16.f32 "
        "{%0,%1,%2,%3}, {%4,%5,%6,%7}, {%8,%9}, {%0,%1,%2,%3};\n"
        : "+f"(c[0]), "+f"(c[1]), "+f"(c[2]), "+f"(c[3])
        : "r"(a[0]), "r"(a[1]), "r"(a[2]), "r"(a[3]), "r"(b0), "r"(b1));
}

// ---------------------------------------------------------------------------
// Kernel 0: pre-convert Wih0 -> hi/lo f16x2 planes (GEMM Bs layout)
// ---------------------------------------------------------------------------
__global__ __launch_bounds__(256) void prep_w(
    const float* __restrict__ Wih0, uint32_t* __restrict__ wprep)
{
    int u = blockIdx.x * 256 + threadIdx.x;
    int n = u >> 3, kg = u & 7;
    int nc = n >> 6, r = n & 63;
#pragma unroll
    for (int j = 0; j < 16; j++) {
        int p = kg * 16 + j;
        float2 v = *(const float2*)(Wih0 + (size_t)n * F_SZ + 2 * p);
        uint32_t hi, lo;
        cvt_hilo_h(v.x, v.y, hi, lo);
        wprep[((nc * 2 + 0) * 64 + r) * 128 + p] = hi;
        wprep[((nc * 2 + 1) * 64 + r) * 128 + p] = lo;
    }
}

// ---------------------------------------------------------------------------
// Kernel 1: input projection GEMM, fp16 with selective gate precision:
// g-gate chunk (nc==2) uses hi+lo (2 MMA); i/f/o use hi only (1 MMA).
// ---------------------------------------------------------------------------
#define AS_STR 132
#define GEMM_SMEM_U32 (128*AS_STR + 2*64*AS_STR + 256)

__global__ __launch_bounds__(256) void input_gemm(
    const float* __restrict__ x,
    const uint32_t* __restrict__ wprep,
    const float* __restrict__ bih0,
    const float* __restrict__ bhh0,
    float* __restrict__ xw0)
{
    extern __shared__ uint32_t smu[];
    uint32_t* As    = smu;                        // [128][132] x as half2
    uint32_t* Bs_hi = As + 128 * AS_STR;          // [64][132]
    uint32_t* Bs_lo = Bs_hi + 64 * AS_STR;
    float*    sbias = (float*)(Bs_lo + 64 * AS_STR);

    const int tid  = threadIdx.x;
    const int lane = tid & 31;
    const int wid  = tid >> 5;
    const int wm   = wid & 3;
    const int wn   = wid >> 2;
    const int g    = lane >> 2;
    const int t4   = lane & 3;
    const int m0   = blockIdx.x * 128;
    const int tt   = m0 >> 10;

    sbias[tid] = bih0[tid] + bhh0[tid];

    {
        int row = tid >> 1, half = tid & 1;
        int b   = (m0 + row) & 1023;
        const float4* src = (const float4*)(x + ((size_t)b * T_SZ + tt) * F_SZ + half * 128);
        uint32_t* d = As + row * AS_STR + half * 64;
#pragma unroll 8
        for (int q = 0; q < 32; q++) {
            float4 v = src[q];
            d[2 * q]     = f2h2(v.x, v.y);
            d[2 * q + 1] = f2h2(v.z, v.w);
        }
    }

#pragma unroll
    for (int nc = 0; nc < 4; nc++) {
        const int n0 = nc * 64;
        {
            int row = tid >> 2, q4 = tid & 3;
            const float4* shi = (const float4*)(wprep + ((nc * 2 + 0) * 64 + row) * 128 + q4 * 32);
            float4* dhi = (float4*)(Bs_hi + row * AS_STR + q4 * 32);
#pragma unroll
            for (int q = 0; q < 8; q++) dhi[q] = shi[q];
            if (nc == 2) {
                const float4* slo = (const float4*)(wprep + ((nc * 2 + 1) * 64 + row) * 128 + q4 * 32);
                float4* dlo = (float4*)(Bs_lo + row * AS_STR + q4 * 32);
#pragma unroll
                for (int q = 0; q < 8; q++) dlo[q] = slo[q];
            }
        }
        __syncthreads();

        float acc[2][4][4];
#pragma unroll
        for (int mi = 0; mi < 2; mi++)
#pragma unroll
            for (int ni = 0; ni < 4; ni++)
#pragma unroll
                for (int q = 0; q < 4; q++) acc[mi][ni][q] = 0.f;

#pragma unroll 4
        for (int ks = 0; ks < 16; ks++) {
            uint32_t a[2][4];
#pragma unroll
            for (int mi = 0; mi < 2; mi++) {
                const uint32_t* p = As + (wm * 32 + mi * 16 + g) * AS_STR + ks * 8 + t4;
                a[mi][0] = p[0];            a[mi][2] = p[4];
                a[mi][1] = p[8 * AS_STR];   a[mi][3] = p[8 * AS_STR + 4];
            }
#pragma unroll
            for (int ni = 0; ni < 4; ni++) {
                int n = wn * 32 + ni * 8 + g;
                uint32_t bh0 = Bs_hi[n * AS_STR + ks * 8 + t4];
                uint32_t bh1 = Bs_hi[n * AS_STR + ks * 8 + t4 + 4];
#pragma unroll
                for (int mi = 0; mi < 2; mi++)
                    mma16816(acc[mi][ni], a[mi], bh0, bh1);
                if (nc == 2) {
                    uint32_t bl0 = Bs_lo[n * AS_STR + ks * 8 + t4];
                    uint32_t bl1 = Bs_lo[n * AS_STR + ks * 8 + t4 + 4];
#pragma unroll
                    for (int mi = 0; mi < 2; mi++)
                        mma16816(acc[mi][ni], a[mi], bl0, bl1);
                }
            }
        }

#pragma unroll
        for (int mi = 0; mi < 2; mi++) {
#pragma unroll
            for (int ni = 0; ni < 4; ni++) {
                int r  = wm * 32 + mi * 16 + g;
                int cl = n0 + wn * 32 + ni * 8 + 2 * t4;
                size_t m = (size_t)(m0 + r);
                xw0[m * G4H + cl]           = acc[mi][ni][0] + sbias[cl];
                xw0[m * G4H + cl + 1]       = acc[mi][ni][1] + sbias[cl + 1];
                xw0[(m + 8) * G4H + cl]     = acc[mi][ni][2] + sbias[cl];
                xw0[(m + 8) * G4H + cl + 1] = acc[mi][ni][3] + sbias[cl + 1];
            }
        }
        __syncthreads();
    }
}

// ---------------------------------------------------------------------------
// Kernel 2: fused 2-layer LSTM recurrence, v6: k-sliced tiling + selective
// gate precision. ntl = gate index (0=i,1=f,2=g,3=o); only ntl==2 (tanh
// input) gets the weight-lo MMA. 60 MMA/warp/step (was 96).
// ---------------------------------------------------------------------------
#define LROWS 8
// smem u32: W2hi 8192 | W2lo 8192 | h0[2][288] | h1[2][288] | bias 256
#define LSTM6_SMEM_U32 (16384 + 4*288 + 256)

__global__ __launch_bounds__(256, 1) void lstm_mma(
    const float* __restrict__ xw0,
    const float* __restrict__ Whh0,
    const float* __restrict__ Wih1,
    const float* __restrict__ Whh1,
    const float* __restrict__ bih1,
    const float* __restrict__ bhh1,
    float* __restrict__ hout)
{
    extern __shared__ uint32_t su[];
    uint32_t* W2hi  = su;
    uint32_t* W2lo  = su + 8192;
    uint32_t* h0buf = su + 16384;            // [2][288] half2
    uint32_t* h1buf = su + 16384 + 576;      // [2][288]
    float*    sbias = (float*)(su + 16384 + 1152);   // [256]

    const int tid  = threadIdx.x;
    const int lane = tid & 31;
    const int w    = tid >> 5;       // warp 0..7 -> k-slice [8w, 8w+8)
    const int g    = lane >> 2;      // row 0..7
    const int t4   = lane & 3;
    const int b0   = blockIdx.x * LROWS;
    const int kp   = 4 * w + t4;     // thread's h kpair (0..31)
    const int kk   = 8 * w + 2 * t4; // thread's k (even)

    // ---- one-time: W2 hi/lo into swizzled smem B-layout ----
    for (int p = tid; p < 8192; p += 256) {
        int n = p >> 5, kpp = p & 31;
        float2 v = *(const float2*)(Whh1 + (size_t)n * 64 + 2 * kpp);
        uint32_t hi, lo;
        cvt_hilo_h(v.x, v.y, hi, lo);
        int col = kpp ^ ((n & 7) << 2);
        W2hi[n * 32 + col] = hi;
        W2lo[n * 32 + col] = lo;
    }
    sbias[tid] = bih1[tid] + bhh1[tid];
    for (int i = tid; i < 1152; i += 256) su[16384 + i] = 0;   // zero h state

    // ---- one-time: W0/W1 B-fragments into registers ----
    // hi for all gates; lo only for gate ntl==2 (g gate).
    uint32_t w0h[4][4][2], w1h[4][4][2];    // [kt][ntl][pos]
    uint32_t w0l[4][2],    w1l[4][2];       // [kt][pos]  (ntl==2 only)
#pragma unroll
    for (int kt = 0; kt < 4; kt++)
#pragma unroll
        for (int ntl = 0; ntl < 4; ntl++) {
            int n  = ntl * 64 + 8 * w + g;
            int p0 = 8 * kt + t4;
            {
                float2 v0 = *(const float2*)(Whh0 + (size_t)n * 64 + 2 * p0);
                float2 v1 = *(const float2*)(Whh0 + (size_t)n * 64 + 2 * (p0 + 4));
                uint32_t h0a, l0a, h1a, l1a;
                cvt_hilo_h(v0.x, v0.y, h0a, l0a);
                cvt_hilo_h(v1.x, v1.y, h1a, l1a);
                w0h[kt][ntl][0] = h0a;  w0h[kt][ntl][1] = h1a;
                if (ntl == 2) { w0l[kt][0] = l0a; w0l[kt][1] = l1a; }
            }
            {
                float2 u0 = *(const float2*)(Wih1 + (size_t)n * 64 + 2 * p0);
                float2 u1 = *(const float2*)(Wih1 + (size_t)n * 64 + 2 * (p0 + 4));
                uint32_t h0a, l0a, h1a, l1a;
                cvt_hilo_h(u0.x, u0.y, h0a, l0a);
                cvt_hilo_h(u1.x, u1.y, h1a, l1a);
                w1h[kt][ntl][0] = h0a;  w1h[kt][ntl][1] = h1a;
                if (ntl == 2) { w1l[kt][0] = l0a; w1l[kt][1] = l1a; }
            }
        }
    __syncthreads();

    float2 bz[4];
#pragma unroll
    for (int gi = 0; gi < 4; gi++)
        bz[gi] = *(const float2*)&sbias[gi * 64 + kk];

    float c0x = 0.f, c0y = 0.f, c1x = 0.f, c1y = 0.f;

    const float* xrow = xw0 + (size_t)(b0 + g) * G4H + kk;
    float2 xq[4];
#pragma unroll
    for (int gi = 0; gi < 4; gi++) xq[gi] = *(const float2*)(xrow + gi * 64);

    for (int t = 0; t < T_SZ; t++) {
        const uint32_t* h0r = h0buf + (t & 1) * 288;
        uint32_t*       h0w = h0buf + ((t + 1) & 1) * 288;
        const uint32_t* h1r = h1buf + (t & 1) * 288;
        uint32_t*       h1w = h1buf + ((t + 1) & 1) * 288;

        // ======= phase A: z0 = Whh0 @ h0_old + gates0 =====================
        float acc0[4][4];
#pragma unroll
        for (int ntl = 0; ntl < 4; ntl++)
#pragma unroll
            for (int q = 0; q < 4; q++) acc0[ntl][q] = 0.f;

#pragma unroll
        for (int kt = 0; kt < 4; kt++) {
            uint32_t a[4];
            {
                const uint32_t* p = h0r + g * 36 + kt * 8 + t4;
                a[0] = p[0]; a[1] = 0u; a[2] = p[4]; a[3] = 0u;
            }
#pragma unroll
            for (int ntl = 0; ntl < 4; ntl++)
                mma16816(acc0[ntl], a, w0h[kt][ntl][0], w0h[kt][ntl][1]);
            mma16816(acc0[2], a, w0l[kt][0], w0l[kt][1]);   // g-gate lo
        }
        {
            float hx, hy;
            {
                float vi = acc0[0][0] + xq[0].x, vf = acc0[1][0] + xq[1].x;
                float vg = acc0[2][0] + xq[2].x, vo = acc0[3][0] + xq[3].x;
                c0x = sigf(vf) * c0x + sigf(vi) * tanhfast(vg);
                hx = sigf(vo) * tanhfast(c0x);
            }
            {
                float vi = acc0[0][1] + xq[0].y, vf = acc0[1][1] + xq[1].y;
                float vg = acc0[2][1] + xq[2].y, vo = acc0[3][1] + xq[3].y;
                c0y = sigf(vf) * c0y + sigf(vi) * tanhfast(vg);
                hy = sigf(vo) * tanhfast(c0y);
            }
            h0w[g * 36 + kp] = f2h2(hx, hy);
        }
        __syncthreads();   // B1: h0_new visible

        // ======= phase B: z1 = Whh1 @ h1_old + Wih1 @ h0_new + gates1 ====
        float acc1[4][4];
#pragma unroll
        for (int ntl = 0; ntl < 4; ntl++)
#pragma unroll
            for (int q = 0; q < 4; q++) acc1[ntl][q] = 0.f;

#pragma unroll
        for (int kt = 0; kt < 4; kt++) {
            uint32_t a[4];
            {
                const uint32_t* p = h1r + g * 36 + kt * 8 + t4;
                a[0] = p[0]; a[1] = 0u; a[2] = p[4]; a[3] = 0u;
            }
            const int cA = (kt * 8 + t4) ^ (g << 2);
            const int cB = (kt * 8 + t4 + 4) ^ (g << 2);
#pragma unroll
            for (int ntl = 0; ntl < 4; ntl++) {
                int n = ntl * 64 + 8 * w + g;
                mma16816(acc1[ntl], a, W2hi[n * 32 + cA], W2hi[n * 32 + cB]);
            }
            {
                int n = 2 * 64 + 8 * w + g;   // g-gate lo
                mma16816(acc1[2], a, W2lo[n * 32 + cA], W2lo[n * 32 + cB]);
            }
        }
#pragma unroll
        for (int kt = 0; kt < 4; kt++) {
            uint32_t a[4];
            {
                const uint32_t* p = h0w + g * 36 + kt * 8 + t4;
                a[0] = p[0]; a[1] = 0u; a[2] = p[4]; a[3] = 0u;
            }
#pragma unroll
            for (int ntl = 0; ntl < 4; ntl++)
                mma16816(acc1[ntl], a, w1h[kt][ntl][0], w1h[kt][ntl][1]);
            mma16816(acc1[2], a, w1l[kt][0], w1l[kt][1]);   // g-gate lo
        }
        {
            float hx, hy;
            {
                float vi = acc1[0][0] + bz[0].x, vf = acc1[1][0] + bz[1].x;
                float vg = acc1[2][0] + bz[2].x, vo = acc1[3][0] + bz[3].x;
                c1x = sigf(vf) * c1x + sigf(vi) * tanhfast(vg);
                hx = sigf(vo) * tanhfast(c1x);
            }
            {
                float vi = acc1[0][1] + bz[0].y, vf = acc1[1][1] + bz[1].y;
                float vg = acc1[2][1] + bz[2].y, vo = acc1[3][1] + bz[3].y;
                c1y = sigf(vf) * c1y + sigf(vi) * tanhfast(vg);
                hy = sigf(vo) * tanhfast(c1y);
            }
            h1w[g * 36 + kp] = f2h2(hx, hy);
            if (t == T_SZ - 1)
                *(float2*)&hout[(size_t)(b0 + g) * H_SZ + kk] = make_float2(hx, hy);
        }
        if (t < T_SZ - 1) {
            size_t off = (size_t)(t + 1) * ((size_t)B_SZ * G4H);
#pragma unroll
            for (int gi = 0; gi < 4; gi++) xq[gi] = *(const float2*)(xrow + off + gi * 64);
        }
        __syncthreads();   // B2: h1_new visible; buffers safe to rotate
    }
}

// ---------------------------------------------------------------------------
// Kernel 3: batchnorm statistics
// ---------------------------------------------------------------------------
__global__ __launch_bounds__(256) void bn_stats(
    const float* __restrict__ h, float* __restrict__ mean, float* __restrict__ rstd)
{
    const int k = blockIdx.x;
    __shared__ float s1[256], s2[256];
    float a = 0.f, b = 0.f;
    for (int i = threadIdx.x; i < B_SZ; i += 256) {
        float v = h[(size_t)i * H_SZ + k];
        a += v; b += v * v;
    }
    s1[threadIdx.x] = a; s2[threadIdx.x] = b;
    __syncthreads();
    for (int s = 128; s > 0; s >>= 1) {
        if (threadIdx.x < s) { s1[threadIdx.x] += s1[threadIdx.x + s]; s2[threadIdx.x] += s2[threadIdx.x + s]; }
        __syncthreads();
    }
    if (threadIdx.x == 0) {
        float m = s1[0] / (float)B_SZ;
        float var = s2[0] / (float)B_SZ - m * m;
        mean[k] = m;
        rstd[k] = rsqrtf(var + 1e-5f);
    }
}

// ---------------------------------------------------------------------------
// Kernel 4: BN apply + MLP trunk + 3 heads
// ---------------------------------------------------------------------------
__global__ __launch_bounds__(256) void mlp_head(
    const float* __restrict__ hbuf,
    const float* __restrict__ mean, const float* __restrict__ rstd,
    const float* __restrict__ gamma, const float* __restrict__ beta,
    const float* __restrict__ W1, const float* __restrict__ b1,
    const float* __restrict__ W2, const float* __restrict__ b2,
    const float* __restrict__ Wmc, const float* __restrict__ bmc,
    const float* __restrict__ Wco, const float* __restrict__ bco,
    const float* __restrict__ Wip, const float* __restrict__ bip,
    float* __restrict__ out)
{
    __shared__ float sH[32][64];
    __shared__ float sY1[32][64];
    __shared__ float sY2[32][32];
    __shared__ float sW1[64 * 64];
    __shared__ float sW2[32 * 64];
    __shared__ float sWh[7 * 32];
    __shared__ float sB1[64], sB2[32], sBh[7];

    const int tid = threadIdx.x;
    const int r0  = blockIdx.x * 32;

    for (int i = tid; i < 64 * 64; i += 256) sW1[i] = W1[i];
    for (int i = tid; i < 32 * 64; i += 256) sW2[i] = W2[i];
    for (int i = tid; i < 7 * 32; i += 256)
        sWh[i] = (i < 96) ? Wmc[i] : (i < 160 ? Wco[i - 96] : Wip[i - 160]);
    if (tid < 64) sB1[tid] = b1[tid];
    if (tid < 32) sB2[tid] = b2[tid];
    if (tid < 7)  sBh[tid] = (tid < 3) ? bmc[tid] : (tid < 5 ? bco[tid - 3] : bip[tid - 5]);

    for (int i = tid; i < 32 * 64; i += 256) {
        int r = i >> 6, k = i & 63;
        float v = hbuf[(size_t)(r0 + r) * 64 + k];
        sH[r][k] = (v - mean[k]) * rstd[k] * gamma[k] + beta[k];
    }
    __syncthreads();

    for (int i = tid; i < 32 * 64; i += 256) {
        int r = i >> 6, o = i & 63;
        float a = sB1[o];
#pragma unroll
        for (int k = 0; k < 64; k++) a += sW1[o * 64 + k] * sH[r][k];
        sY1[r][o] = fmaxf(a, 0.f);
    }
    __syncthreads();

    for (int i = tid; i < 32 * 32; i += 256) {
        int r = i >> 5, o = i & 31;
        float a = sB2[o];
#pragma unroll
        for (int k = 0; k < 64; k++) a += sW2[o * 64 + k] * sY1[r][k];
        sY2[r][o] = fmaxf(a, 0.f);
    }
    __syncthreads();

    for (int i = tid; i < 32 * 7; i += 256) {
        int r = i / 7, o = i % 7;
        float a = sBh[o];
#pragma unroll
        for (int k = 0; k < 32; k++) a += sWh[o * 32 + k] * sY2[r][k];
        int row = r0 + r;
        if (o < 3)       out[(size_t)row * 3 + o] = a;
        else if (o < 5)  out[3072 + (size_t)row * 2 + (o - 3)] = a;
        else             out[5120 + (size_t)row * 2 + (o - 5)] = a;
    }
}

// ---------------------------------------------------------------------------
// Launch
// ---------------------------------------------------------------------------
extern "C" void kernel_launch(void* const* d_in, const int* in_sizes, int n_in,
                              void* d_out, int out_size)
{
    const float* x      = (const float*)d_in[0];
    const float* Wih0   = (const float*)d_in[1];
    const float* Whh0   = (const float*)d_in[2];
    const float* bih0   = (const float*)d_in[3];
    const float* bhh0   = (const float*)d_in[4];
    const float* Wih1   = (const float*)d_in[5];
    const float* Whh1   = (const float*)d_in[6];
    const float* bih1   = (const float*)d_in[7];
    const float* bhh1   = (const float*)d_in[8];
    const float* gamma  = (const float*)d_in[9];
    const float* beta   = (const float*)d_in[10];
    const float* W_fc1  = (const float*)d_in[11];
    const float* b_fc1  = (const float*)d_in[12];
    const float* W_fc2  = (const float*)d_in[13];
    const float* b_fc2  = (const float*)d_in[14];
    const float* W_mc   = (const float*)d_in[15];
    const float* b_mc   = (const float*)d_in[16];
    const float* W_co   = (const float*)d_in[17];
    const float* b_co   = (const float*)d_in[18];
    const float* W_ip   = (const float*)d_in[19];
    const float* b_ip   = (const float*)d_in[20];
    float* out = (float*)d_out;

    float* xw0;       cudaGetSymbolAddress((void**)&xw0,   g_xw0);
    float* hout;      cudaGetSymbolAddress((void**)&hout,  g_hout);
    float* mean;      cudaGetSymbolAddress((void**)&mean,  g_mean);
    float* rstd;      cudaGetSymbolAddress((void**)&rstd,  g_rstd);
    uint32_t* wprep;  cudaGetSymbolAddress((void**)&wprep, g_wprep);

    // 0. pre-convert Wih0 -> hi/lo f16x2 (GEMM B layout)
    prep_w<<<8, 256>>>(Wih0, wprep);

    // 1. input projection GEMM (fp16, selective gate precision)
    {
        size_t smem = (size_t)GEMM_SMEM_U32 * sizeof(uint32_t);
        cudaFuncSetAttribute(input_gemm, cudaFuncAttributeMaxDynamicSharedMemorySize, (int)smem);
        input_gemm<<<(T_SZ * B_SZ) / 128, 256, smem>>>(x, wprep, bih0, bhh0, xw0);
    }

    // 2. fused 2-layer recurrence (fp16, selective gate precision)
    {
        size_t smem = (size_t)LSTM6_SMEM_U32 * sizeof(uint32_t);
        cudaFuncSetAttribute(lstm_mma, cudaFuncAttributeMaxDynamicSharedMemorySize, (int)smem);
        lstm_mma<<<B_SZ / LROWS, 256, smem>>>(xw0, Whh0, Wih1, Whh1, bih1, bhh1, hout);
    }

    // 3. batchnorm statistics
    bn_stats<<<H_SZ, 256>>>(hout, mean, rstd);

    // 4. BN apply + MLP + heads
    mlp_head<<<B_SZ / 32, 256>>>(hout, mean, rstd, gamma, beta,
                                 W_fc1, b_fc1, W_fc2, b_fc2,
                                 W_mc, b_mc, W_co, b_co, W_ip, b_ip, out);
}